// round 7
// baseline (speedup 1.0000x reference)
#include <cuda_runtime.h>
#include <math.h>

#define AN 5
#define NCL 20
#define FD 38
#define SS 1444            // FD*FD
#define MAXB 32
#define MAXO 64
#define IGN 0.6f
#define NSA (AN*SS)        // 7220
#define QP2 (NSA/2)        // 3610 threads per batch (2 positions each)
#define NPB 15             // ceil(3610/256) partial blocks per batch
#define PSTR 16            // partial stride (padded)

// ---------------- scratch (device globals; no allocation) ----------------
__device__ float g_p0[MAXB*PSTR];   // per-block sum conf^2 (all)
__device__ float g_p1[MAXB*PSTR];   // per-block sum conf^2 (maxIoU >= 0.6)
__device__ int   g_pa[MAXB*PSTR];   // per-block any(maxIoU > 0.6)
__device__ float g_w0[MAXB];        // winner: box + class + 25*(conf-mi)^2
__device__ float g_wa[MAXB];        // winner: sum conf^2 (all winners)
__device__ float g_wg[MAXB];        // winner: sum conf^2 (winners with mi >= 0.6)
__device__ unsigned int g_cnt = 0;  // last-block ticket (reset by last block)

__device__ __forceinline__ float sigfast(float x) { return 1.0f / (1.0f + __expf(-x)); }
__device__ __forceinline__ float sigacc (float x) { return 1.0f / (1.0f + expf(-x)); }

__global__ void __launch_bounds__(256) yolo_fused(const float* __restrict__ outp,
                                                  const float* __restrict__ tgt,
                                                  const float* __restrict__ anch,
                                                  float* __restrict__ out,
                                                  int B, int O)
{
    const int b = blockIdx.y;
    const int role = blockIdx.x;          // 0..NPB-1: conf partials, NPB: assignment

    __shared__ float4 sbox[MAXO];
    __shared__ float  sga [MAXO];         // role<NPB: 0.375*area ; role==NPB: area
    __shared__ int    snv;
    __shared__ int    sidx[256];
    __shared__ float  r0[256], r1[256], r2[256];
    __shared__ int    s_last;

    if (threadIdx.x == 0) snv = 0;
    __syncthreads();

    // ---- compact valid GT boxes into smem (order-independent consumers) ----
    const bool k1role = (role < NPB);
    for (int o = threadIdx.x; o < O; o += blockDim.x) {
        const float* tr = tgt + (size_t)(b*O + o)*5;
        float cx = tr[0], cy = tr[1], w = tr[2], h = tr[3], cl = tr[4];
        if (cx + cy + w + h + cl > 0.0f) {
            int k = atomicAdd(&snv, 1);
            float gx = cx*FD, gy = cy*FD, gw = w*FD, gh = h*FD;
            sbox[k] = make_float4(gx - gw*0.5f, gy - gh*0.5f, gx + gw*0.5f, gy + gh*0.5f);
            sga[k]  = k1role ? 0.375f*(gw*gh) : (gw*gh);
        }
    }
    __syncthreads();
    const int nv = snv;

    if (k1role) {
        // ================= role A: conf^2 partials + threshold flags =================
        float csum = 0.0f, cge = 0.0f;
        int anygt = 0;

        int q = role*blockDim.x + threadIdx.x;
        if (q < QP2) {
            int sa = q*2;                 // SS even -> both positions share anchor
            int a = sa / SS, s = sa - a*SS;
            const float* ob = outp + ((size_t)(b*AN + a)*(5+NCL))*SS + s;
            float2 tx = *(const float2*)(ob);
            float2 ty = *(const float2*)(ob + SS);
            float2 tw = *(const float2*)(ob + 2*SS);
            float2 th = *(const float2*)(ob + 3*SS);
            float2 tc = *(const float2*)(ob + 4*SS);
            float aw = anch[2*a]*FD, ah = anch[2*a+1]*FD;

            float px1[2], px2[2], py1[2], py2[2], tpa[2], m[2];
            int j0 = s % FD, i0 = s / FD;
            #pragma unroll
            for (int k = 0; k < 2; k++) {
                int j = j0 + k, i = i0;
                if (j >= FD) { j -= FD; i += 1; }
                float cxp = sigfast((&tx.x)[k]) + (float)j;
                float cyp = sigfast((&ty.x)[k]) + (float)i;
                float pw = __expf((&tw.x)[k])*aw;
                float ph = __expf((&th.x)[k])*ah;
                px1[k] = cxp - pw*0.5f; px2[k] = cxp + pw*0.5f;
                py1[k] = cyp - ph*0.5f; py2[k] = cyp + ph*0.5f;
                tpa[k] = 0.375f*(pw*ph + 1e-12f);
                m[k] = -1e30f;
            }

            // iou >= 0.6 <=> inter >= 0.375*(pa+ga+eps); m = max_o(wx*wy - 0.375*ga)
            #pragma unroll 4
            for (int o = 0; o < nv; o++) {
                float4 g = sbox[o];
                float tga = sga[o];
                #pragma unroll
                for (int k = 0; k < 2; k++) {
                    float wx = fminf(px2[k], g.z) - fmaxf(px1[k], g.x);
                    float wy = fmaxf(fminf(py2[k], g.w) - fmaxf(py1[k], g.y), 0.0f);
                    float d = fmaf(wx, wy, -tga);
                    m[k] = fmaxf(m[k], d);
                }
            }

            #pragma unroll
            for (int k = 0; k < 2; k++) {
                float conf = sigfast((&tc.x)[k]);
                float c2 = conf*conf;
                csum += c2;
                if (m[k] >= tpa[k]) cge += c2;
                if (m[k] >  tpa[k]) anygt = 1;
            }
        }

        r0[threadIdx.x] = csum; r1[threadIdx.x] = cge;
        anygt = __syncthreads_or(anygt);
        for (int st = 128; st > 0; st >>= 1) {
            if (threadIdx.x < st) {
                r0[threadIdx.x] += r0[threadIdx.x + st];
                r1[threadIdx.x] += r1[threadIdx.x + st];
            }
            __syncthreads();
        }
        if (threadIdx.x == 0) {
            g_p0[b*PSTR + role] = r0[0];
            g_p1[b*PSTR + role] = r1[0];
            g_pa[b*PSTR + role] = anygt;
        }
    } else {
        // ================= role B: assignment + winner terms =================
        int o = threadIdx.x;
        int myidx = -1, mya = 0;
        float gx = 0.f, gy = 0.f, gw = 0.f, gh = 0.f, cl = 0.f, ax = 0.f, ay = 0.f;
        if (o < O) {
            const float* tr = tgt + (size_t)(b*O + o)*5;
            float cx = tr[0], cyy = tr[1], w = tr[2], h = tr[3]; cl = tr[4];
            if (cx + cyy + w + h + cl > 0.0f) {
                gx = cx*FD; gy = cyy*FD; gw = w*FD; gh = h*FD;
                float x1 = gx - gw*0.5f, y1 = gy - gh*0.5f;
                float x2 = gx + gw*0.5f, y2 = gy + gh*0.5f;
                int ci = (int)floorf(x1), cj = (int)floorf(y1);
                int cell = min(max(cj*FD + ci, 0), SS - 1);
                ax = (float)(cell % FD) + 0.5f;
                ay = (float)(cell / FD) + 0.5f;
                float ga = gw*gh;
                float best = -1.0f; int ba = 0;
                #pragma unroll
                for (int a2 = 0; a2 < AN; a2++) {
                    float aw = anch[2*a2]*FD, ah = anch[2*a2+1]*FD;
                    float ix = fminf(ax + aw*0.5f, x2) - fmaxf(ax - aw*0.5f, x1);
                    float iy = fminf(ay + ah*0.5f, y2) - fmaxf(ay - ah*0.5f, y1);
                    float inter = fmaxf(ix, 0.0f)*fmaxf(iy, 0.0f);
                    float iou = inter / (aw*ah + ga - inter + 1e-12f);
                    if (iou > best) { best = iou; ba = a2; }
                }
                mya = ba;
                myidx = (b*AN + ba)*SS + cell;
            }
        }
        sidx[threadIdx.x] = myidx;
        __syncthreads();

        // last-write-wins: highest object index keeps the slot
        bool win = (myidx >= 0);
        if (win) {
            for (int o2 = o + 1; o2 < O; o2++)
                if (sidx[o2] == myidx) { win = false; break; }
        }

        float acc = 0.0f, wcall = 0.0f, wcge = 0.0f;
        if (win) {
            int cell = myidx % SS;
            const float* ob = outp + ((size_t)(b*AN + mya)*(5+NCL))*SS + cell;
            float awr = anch[2*mya]*FD, ahr = anch[2*mya+1]*FD;
            int j = cell % FD, i = cell / FD;

            float sxv = sigacc(ob[0]);
            float syv = sigacc(ob[SS]);
            float ewv = expf(ob[2*SS]);
            float ehv = expf(ob[3*SS]);
            float px = sxv + (float)j, py = syv + (float)i;
            float pw = ewv*awr, ph = ehv*ahr;
            float pa = pw*ph;
            float p_x1 = px - pw*0.5f, p_y1 = py - ph*0.5f;
            float p_x2 = px + pw*0.5f, p_y2 = py + ph*0.5f;

            // exact max IoU at this position (iou_target)
            float mi = 0.0f;
            for (int t = 0; t < nv; t++) {
                float4 g = sbox[t];
                float wx = fmaxf(fminf(p_x2, g.z) - fmaxf(p_x1, g.x), 0.0f);
                float wy = fmaxf(fminf(p_y2, g.w) - fmaxf(p_y1, g.y), 0.0f);
                float inter = wx*wy;
                float iou = inter / (pa + sga[t] - inter + 1e-12f);
                mi = fmaxf(mi, iou);
            }

            float conf = sigacc(ob[4*SS]);
            float c2 = conf*conf;
            wcall = c2;
            if (mi >= IGN) wcge = c2;
            float d0 = conf - mi;

            float dx = sxv - (gx - ax);
            float dy = syv - (gy - ay);
            float dw = ewv - gw/awr;
            float dh = ehv - gh/ahr;
            acc = dx*dx + dy*dy + dw*dw + dh*dh + 25.0f*d0*d0;

            // class CE = -log_softmax(softmax(z))[ct], replicated exactly
            float z[NCL];
            float mx = -1e30f;
            #pragma unroll
            for (int c = 0; c < NCL; c++) { z[c] = ob[(5 + c)*SS]; mx = fmaxf(mx, z[c]); }
            float se = 0.0f;
            #pragma unroll
            for (int c = 0; c < NCL; c++) { z[c] = expf(z[c] - mx); se += z[c]; }
            float inv = 1.0f/se;
            float pm = -1e30f;
            #pragma unroll
            for (int c = 0; c < NCL; c++) { z[c] *= inv; pm = fmaxf(pm, z[c]); }
            float se2 = 0.0f;
            #pragma unroll
            for (int c = 0; c < NCL; c++) se2 += expf(z[c] - pm);
            int ct = (int)cl;
            acc += pm + logf(se2) - z[ct];
        }

        r0[threadIdx.x] = acc; r1[threadIdx.x] = wcall; r2[threadIdx.x] = wcge;
        __syncthreads();
        for (int st = 128; st > 0; st >>= 1) {
            if (threadIdx.x < st) {
                r0[threadIdx.x] += r0[threadIdx.x + st];
                r1[threadIdx.x] += r1[threadIdx.x + st];
                r2[threadIdx.x] += r2[threadIdx.x + st];
            }
            __syncthreads();
        }
        if (threadIdx.x == 0) {
            g_w0[b] = r0[0]; g_wa[b] = r1[0]; g_wg[b] = r2[0];
        }
    }

    // ================= last-block final combine =================
    __threadfence();
    if (threadIdx.x == 0) {
        unsigned int total = gridDim.x * gridDim.y;
        unsigned int ticket = atomicAdd(&g_cnt, 1u);
        s_last = (ticket == total - 1u) ? 1 : 0;
    }
    __syncthreads();
    if (s_last) {
        int t = threadIdx.x;
        if (t < 32) {
            float v = 0.0f;
            if (t < B) {
                float t0 = 0.0f, t1 = 0.0f;
                int np = 0;
                #pragma unroll
                for (int i = 0; i < NPB; i++) {
                    t0 += __ldcg(&g_p0[t*PSTR + i]);
                    t1 += __ldcg(&g_p1[t*PSTR + i]);
                    np |= __ldcg(&g_pa[t*PSTR + i]);
                }
                float noobj = t0 - (np ? t1 : 0.0f);
                float wsub  = np ? (__ldcg(&g_wa[t]) - __ldcg(&g_wg[t])) : __ldcg(&g_wa[t]);
                v = noobj + __ldcg(&g_w0[t]) - wsub;
            }
            #pragma unroll
            for (int st = 16; st > 0; st >>= 1) v += __shfl_down_sync(0xffffffff, v, st);
            if (t == 0) {
                out[0] = v / (float)B;
                g_cnt = 0;               // reset for next graph replay
            }
        }
    }
}

// ---------------- launch ----------------
extern "C" void kernel_launch(void* const* d_in, const int* in_sizes, int n_in,
                              void* d_out, int out_size)
{
    const float* outp = (const float*)d_in[0];
    const float* tgt  = (const float*)d_in[1];
    const float* anch = (const float*)d_in[2];
    int B = in_sizes[0] / (AN*(5+NCL)*SS);
    int O = in_sizes[1] / (B*5);
    float* out = (float*)d_out;

    dim3 grid(NPB + 1, B);
    yolo_fused<<<grid, 256>>>(outp, tgt, anch, out, B, O);
}

// round 8
// speedup vs baseline: 1.0047x; 1.0047x over previous
#include <cuda_runtime.h>
#include <math.h>

#define AN 5
#define NCL 20
#define FD 38
#define SS 1444            // FD*FD
#define MAXB 32
#define MAXO 64
#define IGN 0.6f
#define NSA (AN*SS)        // 7220
#define QP2 (NSA/2)        // 3610 threads per batch (2 positions each)
#define NPB 15             // ceil(3610/256) partial blocks per batch
#define PSTR 16            // partial stride (padded)

// ---------------- scratch (device globals; no allocation) ----------------
__device__ float g_p0[MAXB*PSTR];   // per-block sum conf^2 (all)
__device__ float g_p1[MAXB*PSTR];   // per-block sum conf^2 (maxIoU >= 0.6)
__device__ int   g_pa[MAXB*PSTR];   // per-block any(maxIoU > 0.6)
__device__ float g_w0[MAXB];        // winner: box + class + 25*(conf-mi)^2
__device__ float g_wa[MAXB];        // winner: sum conf^2 (all winners)
__device__ float g_wg[MAXB];        // winner: sum conf^2 (winners with mi >= 0.6)
__device__ unsigned int g_cnt = 0;  // last-block ticket (reset by last block)

__device__ __forceinline__ float sigfast(float x) { return 1.0f / (1.0f + __expf(-x)); }
__device__ __forceinline__ float sigacc (float x) { return 1.0f / (1.0f + expf(-x)); }

__global__ void __launch_bounds__(256) yolo_fused(const float* __restrict__ outp,
                                                  const float* __restrict__ tgt,
                                                  const float* __restrict__ anch,
                                                  float* __restrict__ out,
                                                  int B, int O)
{
    const int b = blockIdx.y;
    const int role = blockIdx.x;          // 0..NPB-1: conf partials, NPB: assignment

    __shared__ float4 sbox[MAXO];
    __shared__ float  sga [MAXO];         // role<NPB: 0.375*area ; role==NPB: area
    __shared__ int    snv;
    __shared__ int    sidx[256];
    __shared__ float  r0[256], r1[256], r2[256];
    __shared__ int    s_last;

    if (threadIdx.x == 0) snv = 0;
    __syncthreads();

    // ---- compact valid GT boxes into smem (order-independent consumers) ----
    const bool k1role = (role < NPB);
    for (int o = threadIdx.x; o < O; o += blockDim.x) {
        const float* tr = tgt + (size_t)(b*O + o)*5;
        float cx = tr[0], cy = tr[1], w = tr[2], h = tr[3], cl = tr[4];
        if (cx + cy + w + h + cl > 0.0f) {
            int k = atomicAdd(&snv, 1);
            float gx = cx*FD, gy = cy*FD, gw = w*FD, gh = h*FD;
            sbox[k] = make_float4(gx - gw*0.5f, gy - gh*0.5f, gx + gw*0.5f, gy + gh*0.5f);
            sga[k]  = k1role ? 0.375f*(gw*gh) : (gw*gh);
        }
    }
    __syncthreads();
    const int nv = snv;

    if (k1role) {
        // ================= role A: conf^2 partials + threshold flags =================
        float csum = 0.0f, cge = 0.0f;
        int anygt = 0;

        int q = role*blockDim.x + threadIdx.x;
        if (q < QP2) {
            int sa = q*2;                 // SS even -> both positions share anchor
            int a = sa / SS, s = sa - a*SS;
            const float* ob = outp + ((size_t)(b*AN + a)*(5+NCL))*SS + s;
            float2 tx = *(const float2*)(ob);
            float2 ty = *(const float2*)(ob + SS);
            float2 tw = *(const float2*)(ob + 2*SS);
            float2 th = *(const float2*)(ob + 3*SS);
            float2 tc = *(const float2*)(ob + 4*SS);
            float aw = anch[2*a]*FD, ah = anch[2*a+1]*FD;

            float px1[2], px2[2], py1[2], py2[2], tpa[2], m[2];
            int j0 = s % FD, i0 = s / FD;
            #pragma unroll
            for (int k = 0; k < 2; k++) {
                int j = j0 + k, i = i0;
                if (j >= FD) { j -= FD; i += 1; }
                float cxp = sigfast((&tx.x)[k]) + (float)j;
                float cyp = sigfast((&ty.x)[k]) + (float)i;
                float pw = __expf((&tw.x)[k])*aw;
                float ph = __expf((&th.x)[k])*ah;
                px1[k] = cxp - pw*0.5f; px2[k] = cxp + pw*0.5f;
                py1[k] = cyp - ph*0.5f; py2[k] = cyp + ph*0.5f;
                tpa[k] = 0.375f*(pw*ph + 1e-12f);
                m[k] = -1e30f;
            }

            // iou >= 0.6 <=> inter >= 0.375*(pa+ga+eps); m = max_o(wx*wy - 0.375*ga)
            #pragma unroll 4
            for (int o = 0; o < nv; o++) {
                float4 g = sbox[o];
                float tga = sga[o];
                #pragma unroll
                for (int k = 0; k < 2; k++) {
                    float wx = fminf(px2[k], g.z) - fmaxf(px1[k], g.x);
                    float wy = fmaxf(fminf(py2[k], g.w) - fmaxf(py1[k], g.y), 0.0f);
                    float d = fmaf(wx, wy, -tga);
                    m[k] = fmaxf(m[k], d);
                }
            }

            #pragma unroll
            for (int k = 0; k < 2; k++) {
                float conf = sigfast((&tc.x)[k]);
                float c2 = conf*conf;
                csum += c2;
                if (m[k] >= tpa[k]) cge += c2;
                if (m[k] >  tpa[k]) anygt = 1;
            }
        }

        r0[threadIdx.x] = csum; r1[threadIdx.x] = cge;
        anygt = __syncthreads_or(anygt);
        for (int st = 128; st > 0; st >>= 1) {
            if (threadIdx.x < st) {
                r0[threadIdx.x] += r0[threadIdx.x + st];
                r1[threadIdx.x] += r1[threadIdx.x + st];
            }
            __syncthreads();
        }
        if (threadIdx.x == 0) {
            g_p0[b*PSTR + role] = r0[0];
            g_p1[b*PSTR + role] = r1[0];
            g_pa[b*PSTR + role] = anygt;
        }
    } else {
        // ================= role B: assignment + winner terms =================
        int o = threadIdx.x;
        int myidx = -1, mya = 0;
        float gx = 0.f, gy = 0.f, gw = 0.f, gh = 0.f, cl = 0.f, ax = 0.f, ay = 0.f;
        if (o < O) {
            const float* tr = tgt + (size_t)(b*O + o)*5;
            float cx = tr[0], cyy = tr[1], w = tr[2], h = tr[3]; cl = tr[4];
            if (cx + cyy + w + h + cl > 0.0f) {
                gx = cx*FD; gy = cyy*FD; gw = w*FD; gh = h*FD;
                float x1 = gx - gw*0.5f, y1 = gy - gh*0.5f;
                float x2 = gx + gw*0.5f, y2 = gy + gh*0.5f;
                int ci = (int)floorf(x1), cj = (int)floorf(y1);
                int cell = min(max(cj*FD + ci, 0), SS - 1);
                ax = (float)(cell % FD) + 0.5f;
                ay = (float)(cell / FD) + 0.5f;
                float ga = gw*gh;
                float best = -1.0f; int ba = 0;
                #pragma unroll
                for (int a2 = 0; a2 < AN; a2++) {
                    float aw = anch[2*a2]*FD, ah = anch[2*a2+1]*FD;
                    float ix = fminf(ax + aw*0.5f, x2) - fmaxf(ax - aw*0.5f, x1);
                    float iy = fminf(ay + ah*0.5f, y2) - fmaxf(ay - ah*0.5f, y1);
                    float inter = fmaxf(ix, 0.0f)*fmaxf(iy, 0.0f);
                    float iou = inter / (aw*ah + ga - inter + 1e-12f);
                    if (iou > best) { best = iou; ba = a2; }
                }
                mya = ba;
                myidx = (b*AN + ba)*SS + cell;
            }
        }
        sidx[threadIdx.x] = myidx;
        __syncthreads();

        // last-write-wins: highest object index keeps the slot
        bool win = (myidx >= 0);
        if (win) {
            for (int o2 = o + 1; o2 < O; o2++)
                if (sidx[o2] == myidx) { win = false; break; }
        }

        float acc = 0.0f, wcall = 0.0f, wcge = 0.0f;
        if (win) {
            int cell = myidx % SS;
            const float* ob = outp + ((size_t)(b*AN + mya)*(5+NCL))*SS + cell;
            float awr = anch[2*mya]*FD, ahr = anch[2*mya+1]*FD;
            int j = cell % FD, i = cell / FD;

            float sxv = sigacc(ob[0]);
            float syv = sigacc(ob[SS]);
            float ewv = expf(ob[2*SS]);
            float ehv = expf(ob[3*SS]);
            float px = sxv + (float)j, py = syv + (float)i;
            float pw = ewv*awr, ph = ehv*ahr;
            float pa = pw*ph;
            float p_x1 = px - pw*0.5f, p_y1 = py - ph*0.5f;
            float p_x2 = px + pw*0.5f, p_y2 = py + ph*0.5f;

            // exact max IoU at this position (iou_target)
            float mi = 0.0f;
            for (int t = 0; t < nv; t++) {
                float4 g = sbox[t];
                float wx = fmaxf(fminf(p_x2, g.z) - fmaxf(p_x1, g.x), 0.0f);
                float wy = fmaxf(fminf(p_y2, g.w) - fmaxf(p_y1, g.y), 0.0f);
                float inter = wx*wy;
                float iou = inter / (pa + sga[t] - inter + 1e-12f);
                mi = fmaxf(mi, iou);
            }

            float conf = sigacc(ob[4*SS]);
            float c2 = conf*conf;
            wcall = c2;
            if (mi >= IGN) wcge = c2;
            float d0 = conf - mi;

            float dx = sxv - (gx - ax);
            float dy = syv - (gy - ay);
            float dw = ewv - gw/awr;
            float dh = ehv - gh/ahr;
            acc = dx*dx + dy*dy + dw*dw + dh*dh + 25.0f*d0*d0;

            // class CE = -log_softmax(softmax(z))[ct], replicated exactly
            float z[NCL];
            float mx = -1e30f;
            #pragma unroll
            for (int c = 0; c < NCL; c++) { z[c] = ob[(5 + c)*SS]; mx = fmaxf(mx, z[c]); }
            float se = 0.0f;
            #pragma unroll
            for (int c = 0; c < NCL; c++) { z[c] = expf(z[c] - mx); se += z[c]; }
            float inv = 1.0f/se;
            float pm = -1e30f;
            #pragma unroll
            for (int c = 0; c < NCL; c++) { z[c] *= inv; pm = fmaxf(pm, z[c]); }
            float se2 = 0.0f;
            #pragma unroll
            for (int c = 0; c < NCL; c++) se2 += expf(z[c] - pm);
            int ct = (int)cl;
            acc += pm + logf(se2) - z[ct];
        }

        r0[threadIdx.x] = acc; r1[threadIdx.x] = wcall; r2[threadIdx.x] = wcge;
        __syncthreads();
        for (int st = 128; st > 0; st >>= 1) {
            if (threadIdx.x < st) {
                r0[threadIdx.x] += r0[threadIdx.x + st];
                r1[threadIdx.x] += r1[threadIdx.x + st];
                r2[threadIdx.x] += r2[threadIdx.x + st];
            }
            __syncthreads();
        }
        if (threadIdx.x == 0) {
            g_w0[b] = r0[0]; g_wa[b] = r1[0]; g_wg[b] = r2[0];
        }
    }

    // ================= last-block final combine =================
    __threadfence();
    if (threadIdx.x == 0) {
        unsigned int total = gridDim.x * gridDim.y;
        unsigned int ticket = atomicAdd(&g_cnt, 1u);
        s_last = (ticket == total - 1u) ? 1 : 0;
    }
    __syncthreads();
    if (s_last) {
        int t = threadIdx.x;
        if (t < 32) {
            float v = 0.0f;
            if (t < B) {
                float t0 = 0.0f, t1 = 0.0f;
                int np = 0;
                #pragma unroll
                for (int i = 0; i < NPB; i++) {
                    t0 += __ldcg(&g_p0[t*PSTR + i]);
                    t1 += __ldcg(&g_p1[t*PSTR + i]);
                    np |= __ldcg(&g_pa[t*PSTR + i]);
                }
                float noobj = t0 - (np ? t1 : 0.0f);
                float wsub  = np ? (__ldcg(&g_wa[t]) - __ldcg(&g_wg[t])) : __ldcg(&g_wa[t]);
                v = noobj + __ldcg(&g_w0[t]) - wsub;
            }
            #pragma unroll
            for (int st = 16; st > 0; st >>= 1) v += __shfl_down_sync(0xffffffff, v, st);
            if (t == 0) {
                out[0] = v / (float)B;
                g_cnt = 0;               // reset for next graph replay
            }
        }
    }
}

// ---------------- launch ----------------
extern "C" void kernel_launch(void* const* d_in, const int* in_sizes, int n_in,
                              void* d_out, int out_size)
{
    const float* outp = (const float*)d_in[0];
    const float* tgt  = (const float*)d_in[1];
    const float* anch = (const float*)d_in[2];
    int B = in_sizes[0] / (AN*(5+NCL)*SS);
    int O = in_sizes[1] / (B*5);
    float* out = (float*)d_out;

    dim3 grid(NPB + 1, B);
    yolo_fused<<<grid, 256>>>(outp, tgt, anch, out, B, O);
}